// round 1
// baseline (speedup 1.0000x reference)
#include <cuda_runtime.h>

#define Bn 4
#define Nn 8192
#define Cin 64
#define Sn 2048
#define NS 32
#define R2 0.64f

// Scratch (device globals: no allocation allowed)
__device__ float g_F1[Bn * Nn * 128];   // 16 MB: per-point precomputed W1[:,3:]@features, layout [b][j][o]
__device__ int   g_idx[Bn * Sn * NS];   // ball-query indices
__device__ int   g_cnt[Bn * Sn];        // ball counts

// ---------------------------------------------------------------------------
// FPS: one block per batch, 1024 threads, 8 points/thread in registers.
// Matches jnp.argmax first-occurrence tie-breaking (lowest index wins).
// ---------------------------------------------------------------------------
__global__ __launch_bounds__(1024, 1)
void fps_kernel(const float* __restrict__ xyz, float* __restrict__ new_xyz)
{
    const int b = blockIdx.x;
    const int t = threadIdx.x;
    const float* X = xyz + (size_t)b * Nn * 3;

    float px[8], py[8], pz[8], dst[8];
#pragma unroll
    for (int k = 0; k < 8; k++) {
        int j = k * 1024 + t;
        px[k] = X[j * 3 + 0];
        py[k] = X[j * 3 + 1];
        pz[k] = X[j * 3 + 2];
        dst[k] = 1e10f;
    }

    __shared__ float sval[32];
    __shared__ int   sidx[32];
    __shared__ int   sLast;

    if (t == 0) {
        new_xyz[(b * Sn + 0) * 3 + 0] = X[0];
        new_xyz[(b * Sn + 0) * 3 + 1] = X[1];
        new_xyz[(b * Sn + 0) * 3 + 2] = X[2];
    }

    int last = 0;
    const int lane = t & 31;
    const int w    = t >> 5;

    for (int i = 1; i < Sn; i++) {
        const float qx = X[last * 3 + 0];
        const float qy = X[last * 3 + 1];
        const float qz = X[last * 3 + 2];

        float bestd = -1.0f;
        int   bestj = 0;
#pragma unroll
        for (int k = 0; k < 8; k++) {
            float dx = px[k] - qx;
            float dy = py[k] - qy;
            float dz = pz[k] - qz;
            float d  = dx * dx + dy * dy + dz * dz;
            float nd = fminf(dst[k], d);
            dst[k] = nd;
            if (nd > bestd) { bestd = nd; bestj = k * 1024 + t; }  // k ascending => lower j wins ties
        }
        // warp reduce: max value, lowest index on ties
#pragma unroll
        for (int off = 16; off > 0; off >>= 1) {
            float ov = __shfl_down_sync(0xffffffffu, bestd, off);
            int   oi = __shfl_down_sync(0xffffffffu, bestj, off);
            if (ov > bestd || (ov == bestd && oi < bestj)) { bestd = ov; bestj = oi; }
        }
        if (lane == 0) { sval[w] = bestd; sidx[w] = bestj; }
        __syncthreads();
        if (w == 0) {
            float v = sval[lane];
            int   vi = sidx[lane];
#pragma unroll
            for (int off = 16; off > 0; off >>= 1) {
                float ov = __shfl_down_sync(0xffffffffu, v, off);
                int   oi = __shfl_down_sync(0xffffffffu, vi, off);
                if (ov > v || (ov == v && oi < vi)) { v = ov; vi = oi; }
            }
            if (lane == 0) {
                sLast = vi;
                new_xyz[(b * Sn + i) * 3 + 0] = X[vi * 3 + 0];
                new_xyz[(b * Sn + i) * 3 + 1] = X[vi * 3 + 1];
                new_xyz[(b * Sn + i) * 3 + 2] = X[vi * 3 + 2];
            }
        }
        __syncthreads();
        last = sLast;
    }
}

// ---------------------------------------------------------------------------
// F1 precompute: F1[b][j][o] = sum_c W1[o][3+c] * features[b][c][j]
// block = (b, 64-wide j tile), 256 threads: o = t&127, jhalf = t>>7
// ---------------------------------------------------------------------------
__global__ __launch_bounds__(256)
void f1_kernel(const float* __restrict__ features, const float* __restrict__ w1)
{
    const int b  = blockIdx.x >> 7;      // 128 tiles per batch
    const int jt = blockIdx.x & 127;
    const int j0 = jt * 64;
    const int t  = threadIdx.x;
    const int o  = t & 127;
    const int jh = t >> 7;               // 0/1

    __shared__ float sf[64][64];         // [c][j]
    for (int idx = t; idx < 64 * 64; idx += 256) {
        int c = idx >> 6, j = idx & 63;
        sf[c][j] = features[((size_t)b * Cin + c) * Nn + j0 + j];
    }

    float wr[64];
#pragma unroll
    for (int c = 0; c < 64; c++) wr[c] = w1[o * 67 + 3 + c];
    __syncthreads();

    for (int jg = 0; jg < 8; jg++) {
        const int jb = jh * 32 + jg * 4;
        float a0 = 0.f, a1 = 0.f, a2 = 0.f, a3 = 0.f;
#pragma unroll
        for (int c = 0; c < 64; c++) {
            float4 f = *(const float4*)&sf[c][jb];   // broadcast
            a0 += wr[c] * f.x; a1 += wr[c] * f.y;
            a2 += wr[c] * f.z; a3 += wr[c] * f.w;
        }
        const int j = j0 + jb;
        g_F1[((size_t)b * Nn + j + 0) * 128 + o] = a0;
        g_F1[((size_t)b * Nn + j + 1) * 128 + o] = a1;
        g_F1[((size_t)b * Nn + j + 2) * 128 + o] = a2;
        g_F1[((size_t)b * Nn + j + 3) * 128 + o] = a3;
    }
}

// ---------------------------------------------------------------------------
// Ball query: one warp per query. First NS in-ball indices in ascending
// order; pad with first hit (or 0 if empty). Matches top_k(-score) semantics.
// ---------------------------------------------------------------------------
__global__ __launch_bounds__(256)
void bq_kernel(const float* __restrict__ xyz, const float* __restrict__ new_xyz)
{
    const int gw   = (blockIdx.x * blockDim.x + threadIdx.x) >> 5;
    const int lane = threadIdx.x & 31;
    if (gw >= Bn * Sn) return;
    const int b = gw >> 11;
    const float* X = xyz + (size_t)b * Nn * 3;

    const float qx = new_xyz[gw * 3 + 0];
    const float qy = new_xyz[gw * 3 + 1];
    const float qz = new_xyz[gw * 3 + 2];

    int cnt = 0;
    int myidx = 0;
    for (int base = 0; base < Nn; base += 32) {
        const int j = base + lane;
        float dx = X[j * 3 + 0] - qx;
        float dy = X[j * 3 + 1] - qy;
        float dz = X[j * 3 + 2] - qz;
        float d2 = dx * dx + dy * dy + dz * dz;
        unsigned m = __ballot_sync(0xffffffffu, d2 < R2);
        while (m && cnt < NS) {
            int l = __ffs(m) - 1;
            m &= m - 1;
            if (lane == cnt) myidx = base + l;
            cnt++;
        }
        if (cnt >= NS) break;
    }
    int first = __shfl_sync(0xffffffffu, myidx, 0);
    if (lane >= cnt) myidx = (cnt > 0) ? first : 0;
    g_idx[gw * NS + lane] = myidx;
    if (lane == 0) g_cnt[gw] = cnt;
}

// ---------------------------------------------------------------------------
// MLP + maxpool: one block per query (8192 blocks), 256 threads.
// Stage1: H1[n][o] = relu(F1[idx] + W1xyz.rel + b1)   (o = t&127)
// Stage2: thread t owns output channel o2 = t; W2 row in registers,
//         H1 rows via broadcast LDS.128. Max over 32 samples.
// ---------------------------------------------------------------------------
__global__ __launch_bounds__(256, 1)
void mlp_kernel(const float* __restrict__ xyz, const float* __restrict__ new_xyz,
                const float* __restrict__ w1, const float* __restrict__ b1,
                const float* __restrict__ w2, const float* __restrict__ b2,
                float* __restrict__ pooled)
{
    const int q = blockIdx.x;
    const int b = q >> 11;
    const int s = q & 2047;
    const int t = threadIdx.x;

    __shared__ float H1[NS][128];
    __shared__ float rx[NS], ry[NS], rz[NS];
    __shared__ int   gi[NS];
    __shared__ int   scnt;

    if (t < NS) {
        int id = g_idx[q * NS + t];
        gi[t] = id;
        float qx = new_xyz[q * 3 + 0];
        float qy = new_xyz[q * 3 + 1];
        float qz = new_xyz[q * 3 + 2];
        const float* P = xyz + ((size_t)b * Nn + id) * 3;
        rx[t] = P[0] - qx;
        ry[t] = P[1] - qy;
        rz[t] = P[2] - qz;
    }
    if (t == 0) scnt = g_cnt[q];

    // W2 row -> registers (vectorized)
    float w2r[128];
#pragma unroll
    for (int c = 0; c < 128; c += 4) {
        float4 v = *(const float4*)&w2[(size_t)t * 128 + c];
        w2r[c] = v.x; w2r[c + 1] = v.y; w2r[c + 2] = v.z; w2r[c + 3] = v.w;
    }
    __syncthreads();

    const int cnt = scnt;

    // Stage 1
    {
        const int o  = t & 127;
        const int n0 = (t >> 7) * 16;
        const float w1x = w1[o * 67 + 0];
        const float w1y = w1[o * 67 + 1];
        const float w1z = w1[o * 67 + 2];
        const float bb  = b1[o];
        for (int n = n0; n < n0 + 16; n++) {
            float v;
            if (cnt > 0) {
                int id = gi[n];
                float f = g_F1[((size_t)b * Nn + id) * 128 + o];
                v = f + w1x * rx[n] + w1y * ry[n] + w1z * rz[n] + bb;
            } else {
                v = bb;   // g zeroed for empty balls
            }
            H1[n][o] = fmaxf(v, 0.f);
        }
    }
    __syncthreads();

    // Stage 2 + maxpool
    const float bb2 = b2[t];
    float mx = 0.f;   // relu outputs >= 0
    for (int n = 0; n < NS; n++) {
        float a0 = 0.f, a1 = 0.f, a2 = 0.f, a3 = 0.f;
        const float* h = H1[n];
#pragma unroll
        for (int c = 0; c < 128; c += 4) {
            float4 hv = *(const float4*)&h[c];   // broadcast LDS.128
            a0 += w2r[c + 0] * hv.x;
            a1 += w2r[c + 1] * hv.y;
            a2 += w2r[c + 2] * hv.z;
            a3 += w2r[c + 3] * hv.w;
        }
        float v = fmaxf((a0 + a1) + (a2 + a3) + bb2, 0.f);
        mx = fmaxf(mx, v);
    }
    pooled[((size_t)b * 256 + t) * Sn + s] = mx;
}

// ---------------------------------------------------------------------------
extern "C" void kernel_launch(void* const* d_in, const int* in_sizes, int n_in,
                              void* d_out, int out_size)
{
    const float* xyz      = (const float*)d_in[0];   // (B, N, 3)
    const float* features = (const float*)d_in[1];   // (B, C, N)
    const float* w1       = (const float*)d_in[2];   // (128, 67)
    const float* b1       = (const float*)d_in[3];   // (128)
    const float* w2       = (const float*)d_in[4];   // (256, 128)
    const float* b2       = (const float*)d_in[5];   // (256)

    float* out     = (float*)d_out;
    float* new_xyz = out;                    // (B, S, 3)
    float* pooled  = out + Bn * Sn * 3;      // (B, 256, S)

    fps_kernel<<<Bn, 1024>>>(xyz, new_xyz);
    f1_kernel<<<Bn * 128, 256>>>(features, w1);
    bq_kernel<<<(Bn * Sn * 32 + 255) / 256, 256>>>(xyz, new_xyz);
    mlp_kernel<<<Bn * Sn, 256>>>(xyz, new_xyz, w1, b1, w2, b2, pooled);
}

// round 4
// speedup vs baseline: 1.4234x; 1.4234x over previous
#include <cuda_runtime.h>

#define Bn 4
#define Nn 8192
#define Cin 64
#define Sn 2048
#define NS 32
#define R2 0.64f

// Scratch (device globals — no allocation allowed)
__device__ float g_F1[Bn * Nn * 128];    // per-point W1[:,3:]@features, [b][j][o]
__device__ int   g_idx[Bn * Sn * NS];
__device__ int   g_cnt[Bn * Sn];
__device__ float g_xs[Bn * Nn], g_ys[Bn * Nn], g_zs[Bn * Nn];  // SoA coords
__device__ float g_W2T[128 * 256];       // W2 transposed: [c][o]

// ---------- packed f32x2 helpers ----------
__device__ __forceinline__ unsigned long long pk2(float a, float b) {
    unsigned long long u;
    asm("mov.b64 %0, {%1,%2};" : "=l"(u) : "f"(a), "f"(b));
    return u;
}
__device__ __forceinline__ void upk2(unsigned long long u, float& a, float& b) {
    asm("mov.b64 {%0,%1}, %2;" : "=f"(a), "=f"(b) : "l"(u));
}
__device__ __forceinline__ unsigned long long add2(unsigned long long a, unsigned long long b) {
    unsigned long long r; asm("add.rn.f32x2 %0, %1, %2;" : "=l"(r) : "l"(a), "l"(b)); return r;
}
__device__ __forceinline__ unsigned long long mul2(unsigned long long a, unsigned long long b) {
    unsigned long long r; asm("mul.rn.f32x2 %0, %1, %2;" : "=l"(r) : "l"(a), "l"(b)); return r;
}
__device__ __forceinline__ unsigned long long fma2(unsigned long long a, unsigned long long b,
                                                   unsigned long long c) {
    unsigned long long r; asm("fma.rn.f32x2 %0, %1, %2, %3;" : "=l"(r) : "l"(a), "l"(b), "l"(c)); return r;
}

// ---------------------------------------------------------------------------
// Prep: SoA transpose of xyz + W2 transpose
// ---------------------------------------------------------------------------
__global__ __launch_bounds__(256)
void prep_kernel(const float* __restrict__ xyz, const float* __restrict__ w2)
{
    const int i = blockIdx.x * 256 + threadIdx.x;
    if (i < Bn * Nn) {
        g_xs[i] = xyz[3 * i + 0];
        g_ys[i] = xyz[3 * i + 1];
        g_zs[i] = xyz[3 * i + 2];
    }
    if (i < 256 * 128) {
        const int o = i >> 7, c = i & 127;
        g_W2T[c * 256 + o] = w2[i];
    }
}

// ---------------------------------------------------------------------------
// FPS: one block per batch, 1024 threads, 8 points/thread (packed f32x2).
// Value-only REDUX reduction; index via exact-equality scan + shared atomicMin
// (matches jnp.argmax first-occurrence tie-break).
// ---------------------------------------------------------------------------
__global__ __launch_bounds__(1024, 1)
void fps_kernel(float* __restrict__ new_xyz)
{
    const int b = blockIdx.x;
    const int base = b * Nn;
    const int t = threadIdx.x;
    const int lane = t & 31;
    const int w = t >> 5;

    float x[8], y[8], z[8], dst[8];
#pragma unroll
    for (int k = 0; k < 8; k++) {
        const int j = base + k * 1024 + t;
        x[k] = g_xs[j]; y[k] = g_ys[j]; z[k] = g_zs[j];
        dst[k] = 1e10f;
    }
    unsigned long long X2[4], Y2[4], Z2[4];
#pragma unroll
    for (int g = 0; g < 4; g++) {
        X2[g] = pk2(x[2 * g], x[2 * g + 1]);
        Y2[g] = pk2(y[2 * g], y[2 * g + 1]);
        Z2[g] = pk2(z[2 * g], z[2 * g + 1]);
    }

    __shared__ unsigned int sWmax[32];
    __shared__ unsigned int sGmax;
    __shared__ int sWin;

    float qx = g_xs[base], qy = g_ys[base], qz = g_zs[base];
    if (t == 0) {
        new_xyz[(b * Sn) * 3 + 0] = qx;
        new_xyz[(b * Sn) * 3 + 1] = qy;
        new_xyz[(b * Sn) * 3 + 2] = qz;
    }

    for (int i = 1; i < Sn; i++) {
        const unsigned long long nqx = pk2(-qx, -qx);
        const unsigned long long nqy = pk2(-qy, -qy);
        const unsigned long long nqz = pk2(-qz, -qz);
#pragma unroll
        for (int g = 0; g < 4; g++) {
            unsigned long long dx = add2(X2[g], nqx);
            unsigned long long dy = add2(Y2[g], nqy);
            unsigned long long dz = add2(Z2[g], nqz);
            unsigned long long d  = fma2(dx, dx, fma2(dy, dy, mul2(dz, dz)));
            float dlo, dhi; upk2(d, dlo, dhi);
            dst[2 * g]     = fminf(dst[2 * g], dlo);
            dst[2 * g + 1] = fminf(dst[2 * g + 1], dhi);
        }
        // local max (value only)
        float m0 = fmaxf(dst[0], dst[1]), m1 = fmaxf(dst[2], dst[3]);
        float m2 = fmaxf(dst[4], dst[5]), m3 = fmaxf(dst[6], dst[7]);
        float vmax = fmaxf(fmaxf(m0, m1), fmaxf(m2, m3));

        unsigned int vb = __reduce_max_sync(0xffffffffu, __float_as_uint(vmax));
        if (lane == 0) sWmax[w] = vb;
        __syncthreads();
        if (w == 0) {
            unsigned int gv = __reduce_max_sync(0xffffffffu, sWmax[lane]);
            if (lane == 0) sGmax = gv;
            if (lane == 1) sWin = 0x7fffffff;
        }
        __syncthreads();
        const float gm = __uint_as_float(sGmax);
        int bj = 0x7fffffff;
#pragma unroll
        for (int k = 0; k < 8; k++)
            if (dst[k] == gm) bj = min(bj, k * 1024 + t);
        if (bj != 0x7fffffff) atomicMin(&sWin, bj);
        __syncthreads();
        const int last = sWin;
        qx = g_xs[base + last]; qy = g_ys[base + last]; qz = g_zs[base + last];
        if (t == 0) {
            new_xyz[(b * Sn + i) * 3 + 0] = qx;
            new_xyz[(b * Sn + i) * 3 + 1] = qy;
            new_xyz[(b * Sn + i) * 3 + 2] = qz;
        }
    }
}

// ---------------------------------------------------------------------------
// F1 precompute: F1[b][j][o] = sum_c W1[o][3+c] * features[b][c][j]
// ---------------------------------------------------------------------------
__global__ __launch_bounds__(256)
void f1_kernel(const float* __restrict__ features, const float* __restrict__ w1)
{
    const int b  = blockIdx.x >> 7;
    const int jt = blockIdx.x & 127;
    const int j0 = jt * 64;
    const int t  = threadIdx.x;
    const int o  = t & 127;
    const int jh = t >> 7;

    __shared__ float sf[64][64];
    for (int idx = t; idx < 64 * 64; idx += 256) {
        int c = idx >> 6, j = idx & 63;
        sf[c][j] = features[((size_t)b * Cin + c) * Nn + j0 + j];
    }
    float wr[64];
#pragma unroll
    for (int c = 0; c < 64; c++) wr[c] = w1[o * 67 + 3 + c];
    __syncthreads();

    for (int jg = 0; jg < 8; jg++) {
        const int jb = jh * 32 + jg * 4;
        float a0 = 0.f, a1 = 0.f, a2 = 0.f, a3 = 0.f;
#pragma unroll
        for (int c = 0; c < 64; c++) {
            float4 f = *(const float4*)&sf[c][jb];
            a0 += wr[c] * f.x; a1 += wr[c] * f.y;
            a2 += wr[c] * f.z; a3 += wr[c] * f.w;
        }
        const int j = j0 + jb;
        g_F1[((size_t)b * Nn + j + 0) * 128 + o] = a0;
        g_F1[((size_t)b * Nn + j + 1) * 128 + o] = a1;
        g_F1[((size_t)b * Nn + j + 2) * 128 + o] = a2;
        g_F1[((size_t)b * Nn + j + 3) * 128 + o] = a3;
    }
}

// ---------------------------------------------------------------------------
// Ball query: one warp per query, SoA coalesced loads.
// ---------------------------------------------------------------------------
__global__ __launch_bounds__(256)
void bq_kernel(const float* __restrict__ new_xyz)
{
    const int gw   = (blockIdx.x * blockDim.x + threadIdx.x) >> 5;
    const int lane = threadIdx.x & 31;
    if (gw >= Bn * Sn) return;
    const int b = gw >> 11;
    const int base = b * Nn;

    const float qx = new_xyz[gw * 3 + 0];
    const float qy = new_xyz[gw * 3 + 1];
    const float qz = new_xyz[gw * 3 + 2];

    int cnt = 0;
    int myidx = 0;
    for (int bs = 0; bs < Nn; bs += 32) {
        const int j = base + bs + lane;
        float dx = g_xs[j] - qx;
        float dy = g_ys[j] - qy;
        float dz = g_zs[j] - qz;
        float d2 = dx * dx + dy * dy + dz * dz;
        unsigned m = __ballot_sync(0xffffffffu, d2 < R2);
        while (m && cnt < NS) {
            int l = __ffs(m) - 1;
            m &= m - 1;
            if (lane == cnt) myidx = bs + l;
            cnt++;
        }
        if (cnt >= NS) break;
    }
    int first = __shfl_sync(0xffffffffu, myidx, 0);
    if (lane >= cnt) myidx = (cnt > 0) ? first : 0;
    g_idx[gw * NS + lane] = myidx;
    if (lane == 0) g_cnt[gw] = cnt;
}

// ---------------------------------------------------------------------------
// MLP + maxpool: one block per query, 256 threads, thread t owns output o=t.
// Stage2 streams W2T columns (coalesced, L1-resident) in 16-c chunks, with
// per-sample accumulators acc[32] in registers.
// ---------------------------------------------------------------------------
__global__ __launch_bounds__(256, 2)
void mlp_kernel(const float* __restrict__ new_xyz,
                const float* __restrict__ w1, const float* __restrict__ b1,
                const float* __restrict__ b2, float* __restrict__ pooled)
{
    const int q = blockIdx.x;
    const int b = q >> 11;
    const int s = q & 2047;
    const int t = threadIdx.x;

    __shared__ float H1[NS][128];
    __shared__ float rx[NS], ry[NS], rz[NS];
    __shared__ int   gi[NS];
    __shared__ int   scnt;

    if (t < NS) {
        const int id = g_idx[q * NS + t];
        gi[t] = id;
        const int base = b * Nn;
        rx[t] = g_xs[base + id] - new_xyz[q * 3 + 0];
        ry[t] = g_ys[base + id] - new_xyz[q * 3 + 1];
        rz[t] = g_zs[base + id] - new_xyz[q * 3 + 2];
    }
    if (t == 0) scnt = g_cnt[q];
    __syncthreads();

    const int cnt = scnt;

    // Stage 1: H1[n][o] = relu(F1[id][o] + W1xyz . rel + b1[o])
    {
        const int o  = t & 127;
        const int n0 = (t >> 7) * 16;
        const float w1x = w1[o * 67 + 0];
        const float w1y = w1[o * 67 + 1];
        const float w1z = w1[o * 67 + 2];
        const float bb  = b1[o];
        for (int n = n0; n < n0 + 16; n++) {
            float v;
            if (cnt > 0) {
                const int id = gi[n];
                float f = g_F1[((size_t)b * Nn + id) * 128 + o];
                v = f + w1x * rx[n] + w1y * ry[n] + w1z * rz[n] + bb;
            } else {
                v = bb;
            }
            H1[n][o] = fmaxf(v, 0.f);
        }
    }
    __syncthreads();

    // Stage 2: acc[n] = dot(W2[t], H1[n]); max over n.
    float acc[32];
#pragma unroll
    for (int n = 0; n < 32; n++) acc[n] = 0.f;

    for (int cc = 0; cc < 128; cc += 16) {
        float wv[16];
#pragma unroll
        for (int i = 0; i < 16; i++)
            wv[i] = __ldg(&g_W2T[(cc + i) * 256 + t]);
#pragma unroll
        for (int n = 0; n < 32; n++) {
            const float* h = &H1[n][cc];
            float4 h0 = *(const float4*)(h);
            float4 h1 = *(const float4*)(h + 4);
            float4 h2 = *(const float4*)(h + 8);
            float4 h3 = *(const float4*)(h + 12);
            float a = acc[n];
            a = fmaf(wv[0],  h0.x, a); a = fmaf(wv[1],  h0.y, a);
            a = fmaf(wv[2],  h0.z, a); a = fmaf(wv[3],  h0.w, a);
            a = fmaf(wv[4],  h1.x, a); a = fmaf(wv[5],  h1.y, a);
            a = fmaf(wv[6],  h1.z, a); a = fmaf(wv[7],  h1.w, a);
            a = fmaf(wv[8],  h2.x, a); a = fmaf(wv[9],  h2.y, a);
            a = fmaf(wv[10], h2.z, a); a = fmaf(wv[11], h2.w, a);
            a = fmaf(wv[12], h3.x, a); a = fmaf(wv[13], h3.y, a);
            a = fmaf(wv[14], h3.z, a); a = fmaf(wv[15], h3.w, a);
            acc[n] = a;
        }
    }

    const float bb2 = b2[t];
    float mx = 0.f;
#pragma unroll
    for (int n = 0; n < 32; n++)
        mx = fmaxf(mx, fmaxf(acc[n] + bb2, 0.f));
    pooled[((size_t)b * 256 + t) * Sn + s] = mx;
}

// ---------------------------------------------------------------------------
extern "C" void kernel_launch(void* const* d_in, const int* in_sizes, int n_in,
                              void* d_out, int out_size)
{
    const float* xyz      = (const float*)d_in[0];
    const float* features = (const float*)d_in[1];
    const float* w1       = (const float*)d_in[2];
    const float* b1       = (const float*)d_in[3];
    const float* w2       = (const float*)d_in[4];
    const float* b2       = (const float*)d_in[5];

    float* out     = (float*)d_out;
    float* new_xyz = out;
    float* pooled  = out + Bn * Sn * 3;

    prep_kernel<<<128, 256>>>(xyz, w2);
    f1_kernel<<<Bn * 128, 256>>>(features, w1);
    fps_kernel<<<Bn, 1024>>>(new_xyz);
    bq_kernel<<<(Bn * Sn * 32 + 255) / 256, 256>>>(new_xyz);
    mlp_kernel<<<Bn * Sn, 256>>>(new_xyz, w1, b1, b2, pooled);
}

// round 6
// speedup vs baseline: 1.6521x; 1.1606x over previous
#include <cuda_runtime.h>

#define Bn 4
#define Nn 8192
#define Cin 64
#define Sn 2048
#define NS 32
#define R2 0.64f

// Scratch (device globals — no allocation allowed)
__device__ float g_F1[Bn * Nn * 128];    // per-point W1[:,3:]@features, [b][j][o]
__device__ int   g_idx[Bn * Sn * NS];
__device__ int   g_cnt[Bn * Sn];
__device__ float g_xs[Bn * Nn], g_ys[Bn * Nn], g_zs[Bn * Nn];  // SoA coords (orig order)
__device__ float g_sx[Bn * Nn], g_sy[Bn * Nn], g_sz[Bn * Nn];  // Morton-sorted coords
__device__ int   g_sid[Bn * Nn];                               // sorted -> original index
__device__ float g_W2T[128 * 256];       // W2 transposed: [c][o]

// ---------- packed f32x2 helpers ----------
__device__ __forceinline__ unsigned long long pk2(float a, float b) {
    unsigned long long u;
    asm("mov.b64 %0, {%1,%2};" : "=l"(u) : "f"(a), "f"(b));
    return u;
}
__device__ __forceinline__ void upk2(unsigned long long u, float& a, float& b) {
    asm("mov.b64 {%0,%1}, %2;" : "=f"(a), "=f"(b) : "l"(u));
}
__device__ __forceinline__ unsigned long long add2(unsigned long long a, unsigned long long b) {
    unsigned long long r; asm("add.rn.f32x2 %0, %1, %2;" : "=l"(r) : "l"(a), "l"(b)); return r;
}
__device__ __forceinline__ unsigned long long mul2(unsigned long long a, unsigned long long b) {
    unsigned long long r; asm("mul.rn.f32x2 %0, %1, %2;" : "=l"(r) : "l"(a), "l"(b)); return r;
}
__device__ __forceinline__ unsigned long long fma2(unsigned long long a, unsigned long long b,
                                                   unsigned long long c) {
    unsigned long long r; asm("fma.rn.f32x2 %0, %1, %2, %3;" : "=l"(r) : "l"(a), "l"(b), "l"(c)); return r;
}

// ---------------------------------------------------------------------------
// Prep: SoA transpose of xyz + W2 transpose
// ---------------------------------------------------------------------------
__global__ __launch_bounds__(256)
void prep_kernel(const float* __restrict__ xyz, const float* __restrict__ w2)
{
    const int i = blockIdx.x * 256 + threadIdx.x;
    if (i < Bn * Nn) {
        g_xs[i] = xyz[3 * i + 0];
        g_ys[i] = xyz[3 * i + 1];
        g_zs[i] = xyz[3 * i + 2];
    }
    if (i < 256 * 128) {
        const int o = i >> 7, c = i & 127;
        g_W2T[c * 256 + o] = w2[i];
    }
}

// ---------------------------------------------------------------------------
// Morton counting sort (perf-only permutation; results are exact regardless).
// One block per batch. 8x8x8 grid over fixed [-16,16]^3 (clamped).
// ---------------------------------------------------------------------------
__device__ __forceinline__ int spread3(int v) {
    return (v & 1) | ((v & 2) << 2) | ((v & 4) << 4);
}

__global__ __launch_bounds__(1024, 1)
void fps_sort_kernel()
{
    const int b = blockIdx.x;
    const int base = b * Nn;
    const int t = threadIdx.x;

    __shared__ int h[512];
    __shared__ int off[512];

    if (t < 512) h[t] = 0;
    __syncthreads();

    float px[8], py[8], pz[8];
    int cell[8];
#pragma unroll
    for (int k = 0; k < 8; k++) {
        const int j = base + k * 1024 + t;
        float x = g_xs[j], y = g_ys[j], z = g_zs[j];
        px[k] = x; py[k] = y; pz[k] = z;
        int bx = min(7, max(0, (int)((x + 16.f) * 0.25f)));
        int by = min(7, max(0, (int)((y + 16.f) * 0.25f)));
        int bz = min(7, max(0, (int)((z + 16.f) * 0.25f)));
        cell[k] = (spread3(bx) << 2) | (spread3(by) << 1) | spread3(bz);
        atomicAdd(&h[cell[k]], 1);
    }
    __syncthreads();

    int cnt = 0;
    if (t < 512) cnt = h[t];
    // inclusive Hillis-Steele scan over h[0..511]
    for (int d = 1; d < 512; d <<= 1) {
        int u = 0;
        if (t < 512 && t >= d) u = h[t - d];
        __syncthreads();
        if (t < 512) h[t] += u;
        __syncthreads();
    }
    if (t < 512) off[t] = h[t] - cnt;   // exclusive offset = running cursor
    __syncthreads();

#pragma unroll
    for (int k = 0; k < 8; k++) {
        int pos = atomicAdd(&off[cell[k]], 1);
        g_sx[base + pos] = px[k];
        g_sy[base + pos] = py[k];
        g_sz[base + pos] = pz[k];
        g_sid[base + pos] = k * 1024 + t;
    }
}

// ---------------------------------------------------------------------------
// FPS with exact bucket pruning. One block per batch, 1024 threads, 32 warps.
// Warp w owns sorted chunk [256w, 256w+256). Skip warp update entirely when
// d^2(q, warp bbox) >= warp's current max min-dist (exact no-op condition).
// Candidates carry ORIGINAL indices -> jnp.argmax tie-break preserved exactly.
// ---------------------------------------------------------------------------
__global__ __launch_bounds__(1024, 1)
void fps_kernel(float* __restrict__ new_xyz)
{
    const int b = blockIdx.x;
    const int base = b * Nn;
    const int t = threadIdx.x;
    const int lane = t & 31;
    const int w = t >> 5;

    float dst[8];
    int gid[8];
    float x[8], y[8], z[8];
#pragma unroll
    for (int k = 0; k < 8; k++) {
        const int j = base + w * 256 + k * 32 + lane;
        x[k] = g_sx[j]; y[k] = g_sy[j]; z[k] = g_sz[j];
        gid[k] = g_sid[j];
        dst[k] = 1e10f;
    }

    // warp bbox (one-time)
    float xmn = x[0], xmx = x[0], ymn = y[0], ymx = y[0], zmn = z[0], zmx = z[0];
#pragma unroll
    for (int k = 1; k < 8; k++) {
        xmn = fminf(xmn, x[k]); xmx = fmaxf(xmx, x[k]);
        ymn = fminf(ymn, y[k]); ymx = fmaxf(ymx, y[k]);
        zmn = fminf(zmn, z[k]); zmx = fmaxf(zmx, z[k]);
    }
#pragma unroll
    for (int o = 16; o > 0; o >>= 1) {
        xmn = fminf(xmn, __shfl_xor_sync(0xffffffffu, xmn, o));
        xmx = fmaxf(xmx, __shfl_xor_sync(0xffffffffu, xmx, o));
        ymn = fminf(ymn, __shfl_xor_sync(0xffffffffu, ymn, o));
        ymx = fmaxf(ymx, __shfl_xor_sync(0xffffffffu, ymx, o));
        zmn = fminf(zmn, __shfl_xor_sync(0xffffffffu, zmn, o));
        zmx = fmaxf(zmx, __shfl_xor_sync(0xffffffffu, zmx, o));
    }

    unsigned long long X2[4], Y2[4], Z2[4];
#pragma unroll
    for (int g = 0; g < 4; g++) {
        X2[g] = pk2(x[2 * g], x[2 * g + 1]);
        Y2[g] = pk2(y[2 * g], y[2 * g + 1]);
        Z2[g] = pk2(z[2 * g], z[2 * g + 1]);
    }

    __shared__ float sval[32];
    __shared__ int   sidx[32];
    __shared__ float sq[3];

    float wmax = 1e10f;
    float qx = g_xs[base], qy = g_ys[base], qz = g_zs[base];
    if (t == 0) {
        new_xyz[(b * Sn) * 3 + 0] = qx;
        new_xyz[(b * Sn) * 3 + 1] = qy;
        new_xyz[(b * Sn) * 3 + 2] = qz;
    }

    for (int i = 1; i < Sn; i++) {
        // exact prune test: distance from q to warp bbox
        float dxl = fmaxf(0.f, fmaxf(xmn - qx, qx - xmx));
        float dyl = fmaxf(0.f, fmaxf(ymn - qy, qy - ymx));
        float dzl = fmaxf(0.f, fmaxf(zmn - qz, qz - zmx));
        float dbox = dxl * dxl + dyl * dyl + dzl * dzl;

        if (dbox < wmax) {
            const unsigned long long nqx = pk2(-qx, -qx);
            const unsigned long long nqy = pk2(-qy, -qy);
            const unsigned long long nqz = pk2(-qz, -qz);
#pragma unroll
            for (int g = 0; g < 4; g++) {
                unsigned long long dx = add2(X2[g], nqx);
                unsigned long long dy = add2(Y2[g], nqy);
                unsigned long long dz = add2(Z2[g], nqz);
                unsigned long long d  = fma2(dx, dx, fma2(dy, dy, mul2(dz, dz)));
                float dlo, dhi; upk2(d, dlo, dhi);
                dst[2 * g]     = fminf(dst[2 * g], dlo);
                dst[2 * g + 1] = fminf(dst[2 * g + 1], dhi);
            }
            float m0 = fmaxf(dst[0], dst[1]), m1 = fmaxf(dst[2], dst[3]);
            float m2 = fmaxf(dst[4], dst[5]), m3 = fmaxf(dst[6], dst[7]);
            float vm = fmaxf(fmaxf(m0, m1), fmaxf(m2, m3));

            unsigned gmb = __reduce_max_sync(0xffffffffu, __float_as_uint(vm));
            float gmw = __uint_as_float(gmb);
            int cand = 0x7fffffff;
#pragma unroll
            for (int k = 0; k < 8; k++)
                if (dst[k] == gmw) cand = min(cand, gid[k]);
            int widx = (int)__reduce_min_sync(0xffffffffu, (unsigned)cand);
            if (lane == 0) { sval[w] = gmw; sidx[w] = widx; }
            wmax = gmw;
        }
        __syncthreads();
        if (w == 0) {
            float v = sval[lane];
            int idv = sidx[lane];
            unsigned gmb = __reduce_max_sync(0xffffffffu, __float_as_uint(v));
            int cand = (__float_as_uint(v) == gmb) ? idv : 0x7fffffff;
            int gdx = (int)__reduce_min_sync(0xffffffffu, (unsigned)cand);
            if (lane == 0) {
                float nx = g_xs[base + gdx];
                float ny = g_ys[base + gdx];
                float nz = g_zs[base + gdx];
                sq[0] = nx; sq[1] = ny; sq[2] = nz;
                new_xyz[(b * Sn + i) * 3 + 0] = nx;
                new_xyz[(b * Sn + i) * 3 + 1] = ny;
                new_xyz[(b * Sn + i) * 3 + 2] = nz;
            }
        }
        __syncthreads();
        qx = sq[0]; qy = sq[1]; qz = sq[2];
    }
}

// ---------------------------------------------------------------------------
// F1 precompute: F1[b][j][o] = sum_c W1[o][3+c] * features[b][c][j]
// ---------------------------------------------------------------------------
__global__ __launch_bounds__(256)
void f1_kernel(const float* __restrict__ features, const float* __restrict__ w1)
{
    const int b  = blockIdx.x >> 7;
    const int jt = blockIdx.x & 127;
    const int j0 = jt * 64;
    const int t  = threadIdx.x;
    const int o  = t & 127;
    const int jh = t >> 7;

    __shared__ float sf[64][64];
    for (int idx = t; idx < 64 * 64; idx += 256) {
        int c = idx >> 6, j = idx & 63;
        sf[c][j] = features[((size_t)b * Cin + c) * Nn + j0 + j];
    }
    float wr[64];
#pragma unroll
    for (int c = 0; c < 64; c++) wr[c] = w1[o * 67 + 3 + c];
    __syncthreads();

    for (int jg = 0; jg < 8; jg++) {
        const int jb = jh * 32 + jg * 4;
        float a0 = 0.f, a1 = 0.f, a2 = 0.f, a3 = 0.f;
#pragma unroll
        for (int c = 0; c < 64; c++) {
            float4 f = *(const float4*)&sf[c][jb];
            a0 += wr[c] * f.x; a1 += wr[c] * f.y;
            a2 += wr[c] * f.z; a3 += wr[c] * f.w;
        }
        const int j = j0 + jb;
        g_F1[((size_t)b * Nn + j + 0) * 128 + o] = a0;
        g_F1[((size_t)b * Nn + j + 1) * 128 + o] = a1;
        g_F1[((size_t)b * Nn + j + 2) * 128 + o] = a2;
        g_F1[((size_t)b * Nn + j + 3) * 128 + o] = a3;
    }
}

// ---------------------------------------------------------------------------
// Ball query: one warp per query, SoA coalesced loads.
// ---------------------------------------------------------------------------
__global__ __launch_bounds__(256)
void bq_kernel(const float* __restrict__ new_xyz)
{
    const int gw   = (blockIdx.x * blockDim.x + threadIdx.x) >> 5;
    const int lane = threadIdx.x & 31;
    if (gw >= Bn * Sn) return;
    const int b = gw >> 11;
    const int base = b * Nn;

    const float qx = new_xyz[gw * 3 + 0];
    const float qy = new_xyz[gw * 3 + 1];
    const float qz = new_xyz[gw * 3 + 2];

    int cnt = 0;
    int myidx = 0;
    for (int bs = 0; bs < Nn; bs += 32) {
        const int j = base + bs + lane;
        float dx = g_xs[j] - qx;
        float dy = g_ys[j] - qy;
        float dz = g_zs[j] - qz;
        float d2 = dx * dx + dy * dy + dz * dz;
        unsigned m = __ballot_sync(0xffffffffu, d2 < R2);
        while (m && cnt < NS) {
            int l = __ffs(m) - 1;
            m &= m - 1;
            if (lane == cnt) myidx = bs + l;
            cnt++;
        }
        if (cnt >= NS) break;
    }
    int first = __shfl_sync(0xffffffffu, myidx, 0);
    if (lane >= cnt) myidx = (cnt > 0) ? first : 0;
    g_idx[gw * NS + lane] = myidx;
    if (lane == 0) g_cnt[gw] = cnt;
}

// ---------------------------------------------------------------------------
// MLP + maxpool: one block per query, 256 threads, thread t owns output o=t.
// ---------------------------------------------------------------------------
__global__ __launch_bounds__(256, 2)
void mlp_kernel(const float* __restrict__ new_xyz,
                const float* __restrict__ w1, const float* __restrict__ b1,
                const float* __restrict__ b2, float* __restrict__ pooled)
{
    const int q = blockIdx.x;
    const int b = q >> 11;
    const int s = q & 2047;
    const int t = threadIdx.x;

    __shared__ float H1[NS][128];
    __shared__ float rx[NS], ry[NS], rz[NS];
    __shared__ int   gi[NS];
    __shared__ int   scnt;

    if (t < NS) {
        const int id = g_idx[q * NS + t];
        gi[t] = id;
        const int base = b * Nn;
        rx[t] = g_xs[base + id] - new_xyz[q * 3 + 0];
        ry[t] = g_ys[base + id] - new_xyz[q * 3 + 1];
        rz[t] = g_zs[base + id] - new_xyz[q * 3 + 2];
    }
    if (t == 0) scnt = g_cnt[q];
    __syncthreads();

    const int cnt = scnt;

    // Stage 1: H1[n][o] = relu(F1[id][o] + W1xyz . rel + b1[o])
    {
        const int o  = t & 127;
        const int n0 = (t >> 7) * 16;
        const float w1x = w1[o * 67 + 0];
        const float w1y = w1[o * 67 + 1];
        const float w1z = w1[o * 67 + 2];
        const float bb  = b1[o];
        for (int n = n0; n < n0 + 16; n++) {
            float v;
            if (cnt > 0) {
                const int id = gi[n];
                float f = g_F1[((size_t)b * Nn + id) * 128 + o];
                v = f + w1x * rx[n] + w1y * ry[n] + w1z * rz[n] + bb;
            } else {
                v = bb;
            }
            H1[n][o] = fmaxf(v, 0.f);
        }
    }
    __syncthreads();

    // Stage 2: acc[n] = dot(W2[t], H1[n]); max over n.
    float acc[32];
#pragma unroll
    for (int n = 0; n < 32; n++) acc[n] = 0.f;

    for (int cc = 0; cc < 128; cc += 16) {
        float wv[16];
#pragma unroll
        for (int i = 0; i < 16; i++)
            wv[i] = __ldg(&g_W2T[(cc + i) * 256 + t]);
#pragma unroll
        for (int n = 0; n < 32; n++) {
            const float* h = &H1[n][cc];
            float4 h0 = *(const float4*)(h);
            float4 h1 = *(const float4*)(h + 4);
            float4 h2 = *(const float4*)(h + 8);
            float4 h3 = *(const float4*)(h + 12);
            float a = acc[n];
            a = fmaf(wv[0],  h0.x, a); a = fmaf(wv[1],  h0.y, a);
            a = fmaf(wv[2],  h0.z, a); a = fmaf(wv[3],  h0.w, a);
            a = fmaf(wv[4],  h1.x, a); a = fmaf(wv[5],  h1.y, a);
            a = fmaf(wv[6],  h1.z, a); a = fmaf(wv[7],  h1.w, a);
            a = fmaf(wv[8],  h2.x, a); a = fmaf(wv[9],  h2.y, a);
            a = fmaf(wv[10], h2.z, a); a = fmaf(wv[11], h2.w, a);
            a = fmaf(wv[12], h3.x, a); a = fmaf(wv[13], h3.y, a);
            a = fmaf(wv[14], h3.z, a); a = fmaf(wv[15], h3.w, a);
            acc[n] = a;
        }
    }

    const float bb2 = b2[t];
    float mx = 0.f;
#pragma unroll
    for (int n = 0; n < 32; n++)
        mx = fmaxf(mx, fmaxf(acc[n] + bb2, 0.f));
    pooled[((size_t)b * 256 + t) * Sn + s] = mx;
}

// ---------------------------------------------------------------------------
extern "C" void kernel_launch(void* const* d_in, const int* in_sizes, int n_in,
                              void* d_out, int out_size)
{
    const float* xyz      = (const float*)d_in[0];
    const float* features = (const float*)d_in[1];
    const float* w1       = (const float*)d_in[2];
    const float* b1       = (const float*)d_in[3];
    const float* w2       = (const float*)d_in[4];
    const float* b2       = (const float*)d_in[5];

    float* out     = (float*)d_out;
    float* new_xyz = out;
    float* pooled  = out + Bn * Sn * 3;

    prep_kernel<<<128, 256>>>(xyz, w2);
    fps_sort_kernel<<<Bn, 1024>>>();
    f1_kernel<<<Bn * 128, 256>>>(features, w1);
    fps_kernel<<<Bn, 1024>>>(new_xyz);
    bq_kernel<<<(Bn * Sn * 32 + 255) / 256, 256>>>(new_xyz);
    mlp_kernel<<<Bn * Sn, 256>>>(new_xyz, w1, b1, b2, pooled);
}